// round 9
// baseline (speedup 1.0000x reference)
#include <cuda_runtime.h>

#define D 4096
#define NV4 (D / 4)        // 1024 float4 per row
#define THREADS 256
#define EPS 1e-6f

__device__ __forceinline__ float4 ldcg_asm(const float4* p)
{
    float4 v;
    asm volatile("ld.global.cg.v4.f32 {%0,%1,%2,%3}, [%4];"
                 : "=f"(v.x), "=f"(v.y), "=f"(v.z), "=f"(v.w)
                 : "l"(p));
    return v;
}

__global__ __launch_bounds__(THREADS, 6) void mrmsnorm_kernel(
    const float4* __restrict__ x,
    const float4* __restrict__ scale,
    float4* __restrict__ out)
{
    __shared__ float ws[8][3];

    const int t = threadIdx.x;
    const int warp = t >> 5;
    const int lane = t & 31;

    const size_t row = blockIdx.x;
    const float4* __restrict__ xr = x + row * NV4;
    float4* __restrict__ orow = out + row * NV4;

    // Phase 1: stream the row through registers ONCE, allocate in L2 (ld.cg),
    // keep only the per-segment sums. Data registers are freed immediately.
    float sa, sb, scd;
    {
        float4 a = __ldcg(&xr[t]);
        float4 b = __ldcg(&xr[t + THREADS]);
        float4 c = __ldcg(&xr[t + 2 * THREADS]);
        float4 d = __ldcg(&xr[t + 3 * THREADS]);
        sa  = a.x * a.x + a.y * a.y + a.z * a.z + a.w * a.w;
        sb  = b.x * b.x + b.y * b.y + b.z * b.z + b.w * b.w;
        float sc = c.x * c.x + c.y * c.y + c.z * c.z + c.w * c.w;
        float sd = d.x * d.x + d.y * d.y + d.z * d.z + d.w * d.w;
        scd = sc + sd;
    }

    #pragma unroll
    for (int o = 16; o > 0; o >>= 1) {
        sa  += __shfl_down_sync(0xffffffffu, sa, o);
        sb  += __shfl_down_sync(0xffffffffu, sb, o);
        scd += __shfl_down_sync(0xffffffffu, scd, o);
    }

    if (lane == 0) {
        ws[warp][0] = sa;
        ws[warp][1] = sb;
        ws[warp][2] = scd;
    }
    __syncthreads();

    // Segment sums; float4-index ranges: seg0 [0,64) (warps 0-1),
    // seg1 [64,128) (warps 2-3), seg2 [128,256) (warps 4-7),
    // seg3 [256,512) (slice 1), seg4 [512,1024) (slices 2,3).
    float seg0 = ws[0][0] + ws[1][0];
    float seg1 = ws[2][0] + ws[3][0];
    float seg2 = ws[4][0] + ws[5][0] + ws[6][0] + ws[7][0];
    float seg3 = ws[0][1] + ws[1][1] + ws[2][1] + ws[3][1]
               + ws[4][1] + ws[5][1] + ws[6][1] + ws[7][1];
    float seg4 = ws[0][2] + ws[1][2] + ws[2][2] + ws[3][2]
               + ws[4][2] + ws[5][2] + ws[6][2] + ws[7][2];

    float c0 = seg0;
    float c1 = c0 + seg1;
    float c2 = c1 + seg2;
    float c3 = c2 + seg3;
    float c4 = c3 + seg4;

    float r0 = rsqrtf(c0 * (1.0f / 256.0f)  + EPS);
    float r1 = rsqrtf(c1 * (1.0f / 512.0f)  + EPS);
    float r2 = rsqrtf(c2 * (1.0f / 1024.0f) + EPS);
    float r3 = rsqrtf(c3 * (1.0f / 2048.0f) + EPS);
    float r4 = rsqrtf(c4 * (1.0f / 4096.0f) + EPS);

    float ra = (t < 64) ? r0 : (t < 128) ? r1 : r2;  // warp-uniform
    float rb = r3;
    float rc = r4;

    // Phase 2: re-read the row from L2 (asm prevents CSE back to phase-1 regs),
    // apply rrms * scale, streaming store.
    {
        float4 a = ldcg_asm(&xr[t]);
        float4 s = __ldg(&scale[t]);
        float4 o;
        o.x = a.x * ra * s.x;  o.y = a.y * ra * s.y;
        o.z = a.z * ra * s.z;  o.w = a.w * ra * s.w;
        __stcs(&orow[t], o);
    }
    {
        float4 a = ldcg_asm(&xr[t + THREADS]);
        float4 s = __ldg(&scale[t + THREADS]);
        float4 o;
        o.x = a.x * rb * s.x;  o.y = a.y * rb * s.y;
        o.z = a.z * rb * s.z;  o.w = a.w * rb * s.w;
        __stcs(&orow[t + THREADS], o);
    }
    {
        float4 a = ldcg_asm(&xr[t + 2 * THREADS]);
        float4 s = __ldg(&scale[t + 2 * THREADS]);
        float4 o;
        o.x = a.x * rc * s.x;  o.y = a.y * rc * s.y;
        o.z = a.z * rc * s.z;  o.w = a.w * rc * s.w;
        __stcs(&orow[t + 2 * THREADS], o);
    }
    {
        float4 a = ldcg_asm(&xr[t + 3 * THREADS]);
        float4 s = __ldg(&scale[t + 3 * THREADS]);
        float4 o;
        o.x = a.x * rc * s.x;  o.y = a.y * rc * s.y;
        o.z = a.z * rc * s.z;  o.w = a.w * rc * s.w;
        __stcs(&orow[t + 3 * THREADS], o);
    }
}

extern "C" void kernel_launch(void* const* d_in, const int* in_sizes, int n_in,
                              void* d_out, int out_size)
{
    const float4* x = (const float4*)d_in[0];
    const float4* scale = (const float4*)d_in[1];
    float4* out = (float4*)d_out;

    const int rows = out_size / D;   // 16384
    mrmsnorm_kernel<<<rows, THREADS>>>(x, scale, out);
}

// round 10
// speedup vs baseline: 1.0004x; 1.0004x over previous
#include <cuda_runtime.h>

#define D 4096
#define NV4 (D / 4)        // 1024 float4 per row
#define THREADS 64
#define EPS 1e-6f

__global__ __launch_bounds__(THREADS) void mrmsnorm_kernel(
    const float4* __restrict__ x,
    const float4* __restrict__ scale,
    float4* __restrict__ out)
{
    __shared__ float ws[2][5];   // [warp][segment]

    const int t = threadIdx.x;
    const int warp = t >> 5;
    const int lane = t & 31;

    const size_t row = blockIdx.x;
    const float4* __restrict__ xr = x + row * NV4;
    float4* __restrict__ orow = out + row * NV4;

    // Front-issue all 16 streaming loads. Slice j covers f4 idx [64j, 64j+64)
    // i.e. elements [256j, 256j+256).
    float4 v[16];
    #pragma unroll
    for (int j = 0; j < 16; j++)
        v[j] = __ldcs(&xr[t + j * THREADS]);

    // Per-segment partial sums (slice -> segment map is uniform per slice):
    //   slice 0      -> seg0  [0,256)
    //   slice 1      -> seg1  [256,512)
    //   slices 2-3   -> seg2  [512,1024)
    //   slices 4-7   -> seg3  [1024,2048)
    //   slices 8-15  -> seg4  [2048,4096)
    float p0, p1, p2, p3, p4;
    {
        float sq[16];
        #pragma unroll
        for (int j = 0; j < 16; j++)
            sq[j] = v[j].x * v[j].x + v[j].y * v[j].y
                  + v[j].z * v[j].z + v[j].w * v[j].w;
        p0 = sq[0];
        p1 = sq[1];
        p2 = sq[2] + sq[3];
        p3 = sq[4] + sq[5] + sq[6] + sq[7];
        p4 = (sq[8] + sq[9]) + (sq[10] + sq[11])
           + (sq[12] + sq[13]) + (sq[14] + sq[15]);
    }

    #pragma unroll
    for (int o = 16; o > 0; o >>= 1) {
        p0 += __shfl_down_sync(0xffffffffu, p0, o);
        p1 += __shfl_down_sync(0xffffffffu, p1, o);
        p2 += __shfl_down_sync(0xffffffffu, p2, o);
        p3 += __shfl_down_sync(0xffffffffu, p3, o);
        p4 += __shfl_down_sync(0xffffffffu, p4, o);
    }

    if (lane == 0) {
        ws[warp][0] = p0;
        ws[warp][1] = p1;
        ws[warp][2] = p2;
        ws[warp][3] = p3;
        ws[warp][4] = p4;
    }
    __syncthreads();

    float seg0 = ws[0][0] + ws[1][0];
    float seg1 = ws[0][1] + ws[1][1];
    float seg2 = ws[0][2] + ws[1][2];
    float seg3 = ws[0][3] + ws[1][3];
    float seg4 = ws[0][4] + ws[1][4];

    float c0 = seg0;
    float c1 = c0 + seg1;
    float c2 = c1 + seg2;
    float c3 = c2 + seg3;
    float c4 = c3 + seg4;

    // rrms per slice — fully uniform, no divergence.
    float r[16];
    r[0] = rsqrtf(c0 * (1.0f / 256.0f)  + EPS);
    r[1] = rsqrtf(c1 * (1.0f / 512.0f)  + EPS);
    r[2] = rsqrtf(c2 * (1.0f / 1024.0f) + EPS);
    r[3] = r[2];
    {
        float r3v = rsqrtf(c3 * (1.0f / 2048.0f) + EPS);
        r[4] = r3v; r[5] = r3v; r[6] = r3v; r[7] = r3v;
        float r4v = rsqrtf(c4 * (1.0f / 4096.0f) + EPS);
        #pragma unroll
        for (int j = 8; j < 16; j++) r[j] = r4v;
    }

    #pragma unroll
    for (int j = 0; j < 16; j++) {
        float4 s = __ldg(&scale[t + j * THREADS]);   // L1-resident
        float4 o;
        o.x = v[j].x * r[j] * s.x;
        o.y = v[j].y * r[j] * s.y;
        o.z = v[j].z * r[j] * s.z;
        o.w = v[j].w * r[j] * s.w;
        __stcs(&orow[t + j * THREADS], o);
    }
}

extern "C" void kernel_launch(void* const* d_in, const int* in_sizes, int n_in,
                              void* d_out, int out_size)
{
    const float4* x = (const float4*)d_in[0];
    const float4* scale = (const float4*)d_in[1];
    float4* out = (float4*)d_out;

    const int rows = out_size / D;   // 16384
    mrmsnorm_kernel<<<rows, THREADS>>>(x, scale, out);
}